// round 5
// baseline (speedup 1.0000x reference)
#include <cuda_runtime.h>
#include <cuda_bf16.h>
#include <cstdint>
#include <math.h>

// Problem constants (B=4, T=512, H=1024, V=32000)
#define R_TOK 2048
#define HID   1024
#define VOC   32000
#define NSEQ  4
#define TSEQ  512

#define KCAT  2048              // [hi | lo] storage; 3 term-pairings via offsets
#define BM    128
#define BN    256
#define NBLK  (VOC / BN)        // 125
#define MBLK  (R_TOK / BM)      // 16
#define NCHUNK 48               // 3 passes x 16 chunks of 64 K-elems
#define NSTAGE 4
#define STAGE_BYTES 49152       // A 16KB + B 32KB
#define SMEM_TOTAL (1024 + NSTAGE * STAGE_BYTES)   // 197632

#define BETA 0.1f

// ------------------------------- scratch -----------------------------------
__device__ float g_pm[2][R_TOK][NBLK];
__device__ float g_ps[2][R_TOK][NBLK];
__device__ float g_tgt[2][R_TOK];
__device__ float g_tok[2][R_TOK];
__device__ int   g_target[R_TOK];
__device__ int   g_mask[R_TOK];
__device__ int   g_labels[NSEQ];

__device__ __align__(16) __nv_bfloat16 g_A[2][R_TOK][KCAT];   // 16.8 MB
__device__ __align__(16) __nv_bfloat16 g_B[2][VOC][KCAT];     // 262 MB

// ------------------------------- helpers -----------------------------------
__device__ __forceinline__ uint32_t smem_u32(const void* p) {
    uint32_t a;
    asm("{ .reg .u64 t; cvta.to.shared.u64 t, %1; cvt.u32.u64 %0, t; }"
        : "=r"(a) : "l"(p));
    return a;
}

__device__ __forceinline__ uint32_t sw128(uint32_t o) {
    return o ^ ((o >> 3) & 0x70u);
}

__device__ __forceinline__ void cp16(uint32_t s, const void* g) {
    asm volatile("cp.async.cg.shared.global [%0], [%1], 16;" :: "r"(s), "l"(g));
}

__device__ __forceinline__ void ldsm4(uint32_t& r0, uint32_t& r1,
                                      uint32_t& r2, uint32_t& r3, uint32_t a) {
    asm volatile("ldmatrix.sync.aligned.m8n8.x4.shared.b16 {%0,%1,%2,%3}, [%4];"
                 : "=r"(r0), "=r"(r1), "=r"(r2), "=r"(r3) : "r"(a));
}

__device__ __forceinline__ void hmma(float* c, uint32_t a0, uint32_t a1,
                                     uint32_t a2, uint32_t a3,
                                     uint32_t b0, uint32_t b1) {
    asm volatile(
        "mma.sync.aligned.m16n8k16.row.col.f32.bf16.bf16.f32 "
        "{%0,%1,%2,%3}, {%4,%5,%6,%7}, {%8,%9}, {%0,%1,%2,%3};"
        : "+f"(c[0]), "+f"(c[1]), "+f"(c[2]), "+f"(c[3])
        : "r"(a0), "r"(a1), "r"(a2), "r"(a3), "r"(b0), "r"(b1));
}

// -----------------------------------------------------------------------------
// Phase 0: dtype detection + normalization of target / labels (proven)
// -----------------------------------------------------------------------------
__global__ void detect_kernel(const void* __restrict__ tgt_raw,
                              const void* __restrict__ lab_raw)
{
    __shared__ int s_t64;
    const int tid = threadIdx.x;
    const int* t32 = (const int*)tgt_raw;

    if (tid == 0) {
        bool t64 = true;
        for (int k = 0; k < 64; k++)
            if (t32[2 * k + 1] != 0) { t64 = false; break; }
        s_t64 = t64 ? 1 : 0;

        const unsigned int*  li = (const unsigned int*)lab_raw;
        const unsigned char* lb = (const unsigned char*)lab_raw;
        int done = 0;
        {
            bool isf = true;
            for (int b = 0; b < 4; b++) {
                unsigned int u = li[b];
                if (u != 0u && u != 0x3f800000u) { isf = false; break; }
            }
            if (isf) {
                for (int b = 0; b < 4; b++) g_labels[b] = (li[b] != 0u) ? 1 : 0;
                done = 1;
            }
        }
        if (!done && li[0] <= 1u) {
            bool isi = true;
            for (int b = 1; b < 4; b++)
                if (li[b] > 1u) { isi = false; break; }
            if (isi) {
                for (int b = 0; b < 4; b++) g_labels[b] = (int)li[b];
                done = 1;
            }
        }
        if (!done)
            for (int b = 0; b < 4; b++) g_labels[b] = (lb[b] != 0) ? 1 : 0;
    }
    __syncthreads();

    const bool t64 = (s_t64 != 0);
    for (int i = tid; i < R_TOK; i += blockDim.x) {
        int v = t64 ? t32[2 * i] : t32[i];
        const int ign = (v == -100);
        if (v < 0) v = 0;
        if (v > VOC - 1) v = VOC - 1;
        g_target[i] = v;
        g_mask[i]   = ign ? 0 : 1;
    }
}

// -----------------------------------------------------------------------------
// Phase 0b: fp32 -> bf16 hi/lo split: [hi | lo] (K=2048 each)
// -----------------------------------------------------------------------------
__device__ __forceinline__ void split4(const float4 v,
                                       __nv_bfloat162& h01, __nv_bfloat162& h23,
                                       __nv_bfloat162& l01, __nv_bfloat162& l23)
{
    __nv_bfloat16 h0 = __float2bfloat16_rn(v.x);
    __nv_bfloat16 h1 = __float2bfloat16_rn(v.y);
    __nv_bfloat16 h2 = __float2bfloat16_rn(v.z);
    __nv_bfloat16 h3 = __float2bfloat16_rn(v.w);
    __nv_bfloat16 l0 = __float2bfloat16_rn(v.x - __bfloat162float(h0));
    __nv_bfloat16 l1 = __float2bfloat16_rn(v.y - __bfloat162float(h1));
    __nv_bfloat16 l2 = __float2bfloat16_rn(v.z - __bfloat162float(h2));
    __nv_bfloat16 l3 = __float2bfloat16_rn(v.w - __bfloat162float(h3));
    h01 = __nv_bfloat162(h0, h1); h23 = __nv_bfloat162(h2, h3);
    l01 = __nv_bfloat162(l0, l1); l23 = __nv_bfloat162(l2, l3);
}

__global__ void convert_w_kernel(const float* __restrict__ w0,
                                 const float* __restrict__ w1)
{
    const int QPR = HID / 4;                     // 256 quads/row
    const int per_model = VOC * QPR;
    int id = blockIdx.x * blockDim.x + threadIdx.x;
    if (id >= 2 * per_model) return;
    const int m = id / per_model;
    const int r = (id % per_model) / QPR;
    const int q = id % QPR;
    const float* W = m ? w1 : w0;
    const float4 v = *(const float4*)(W + (size_t)r * HID + q * 4);
    __nv_bfloat162 h01, h23, l01, l23;
    split4(v, h01, h23, l01, l23);
    __nv_bfloat16* row = &g_B[m][r][0];
    *(__nv_bfloat162*)(row + q * 4 + 0)       = h01;   // seg0: hi
    *(__nv_bfloat162*)(row + q * 4 + 2)       = h23;
    *(__nv_bfloat162*)(row + HID + q * 4 + 0) = l01;   // seg1: lo
    *(__nv_bfloat162*)(row + HID + q * 4 + 2) = l23;
}

__global__ void convert_x_kernel(const float* __restrict__ x0,
                                 const float* __restrict__ x1)
{
    const int QPR = HID / 4;
    const int per_model = R_TOK * QPR;
    int id = blockIdx.x * blockDim.x + threadIdx.x;
    if (id >= 2 * per_model) return;
    const int m = id / per_model;
    const int r = (id % per_model) / QPR;
    const int q = id % QPR;
    const float* X = m ? x1 : x0;
    const float4 v = *(const float4*)(X + (size_t)r * HID + q * 4);
    __nv_bfloat162 h01, h23, l01, l23;
    split4(v, h01, h23, l01, l23);
    __nv_bfloat16* row = &g_A[m][r][0];
    *(__nv_bfloat162*)(row + q * 4 + 0)       = h01;   // seg0: hi
    *(__nv_bfloat162*)(row + q * 4 + 2)       = h23;
    *(__nv_bfloat162*)(row + HID + q * 4 + 0) = l01;   // seg1: lo
    *(__nv_bfloat162*)(row + HID + q * 4 + 2) = l23;
}

// -----------------------------------------------------------------------------
// Phase A: HMMA bf16 GEMM, CTA tile 128x256, warp tile 64x64 (2x4 warps).
// 48 chunks of K=64: c<16:(Ahi,Bhi) 16..31:(Ahi,Blo) 32..47:(Alo,Bhi).
// 4-stage cp.async pipeline, loads issued before compute, ldsm double-buffered.
// -----------------------------------------------------------------------------
extern __shared__ char dsmem[];

__global__ void __launch_bounds__(256, 1)
gemm_tc_kernel(const float* __restrict__ b_pol, const float* __restrict__ b_ref)
{
    const int bx    = blockIdx.x;
    const int mblk  = bx & (MBLK - 1);
    const int t     = bx >> 4;
    const int nblk  = t % NBLK;
    const int model = t / NBLK;
    const int rb    = mblk * BM;
    const int cb    = nblk * BN;
    const float* __restrict__ Bv = model ? b_ref : b_pol;

    const int tid = threadIdx.x;
    const int wid = tid >> 5;
    const int lid = tid & 31;

    const uint32_t smem_base = smem_u32(dsmem);

    const char* Agm = (const char*)&g_A[model][rb][0];
    const char* Bgm = (const char*)&g_B[model][cb][0];
    const size_t rowbytes = (size_t)KCAT * 2;   // 4096

    // chunk -> segment offsets (in 128-byte k-units)
    auto a_koff = [](int c) -> int { return (c >= 32) ? 16 + (c & 15) : (c & 15); };
    auto b_koff = [](int c) -> int { return ((c >> 4) == 1) ? 16 + (c & 15) : (c & 15); };

    // ---- tile loader: chunk c -> stage s
    auto load_chunk = [&](int c, int s) {
        const uint32_t abase = smem_base + 1024 + s * STAGE_BYTES;
        const uint32_t bbase = abase + 16384;
        const char* ag = Agm + (size_t)a_koff(c) * 128;
        const char* bg = Bgm + (size_t)b_koff(c) * 128;
        #pragma unroll
        for (int i = 0; i < 4; i++) {               // A: 1024 x 16B
            const int q = tid + 256 * i;
            const int row = q >> 3, x = q & 7;
            cp16(abase + sw128(row * 128 + x * 16), ag + (size_t)row * rowbytes + x * 16);
        }
        #pragma unroll
        for (int i = 0; i < 8; i++) {               // B: 2048 x 16B
            const int q = tid + 256 * i;
            const int row = q >> 3, x = q & 7;
            cp16(bbase + sw128(row * 128 + x * 16), bg + (size_t)row * rowbytes + x * 16);
        }
        asm volatile("cp.async.commit_group;" ::: "memory");
    };

    load_chunk(0, 0);
    load_chunk(1, 1);
    load_chunk(2, 2);

    // warp mapping: 64x64 tiles, 2 (M) x 4 (N)
    const int wr = wid & 1;
    const int wc = wid >> 1;

    // ldsm addressing (same pattern proven in R4)
    const int koffA = (lid >> 4) * 16;
    const int xA    = (lid & 7) << 4;
    const int arow  = wr * 64 + (lid & 15);
    const int rbB   = (lid >> 4) * 8 + (lid & 7);      // 0..15
    const int koffB = ((lid >> 3) & 1) * 16;
    const int xB    = (rbB & 7) << 4;
    const int brow  = wc * 64 + rbB;

    float acc[4][8][4];
    #pragma unroll
    for (int a = 0; a < 4; a++)
        #pragma unroll
        for (int b = 0; b < 8; b++)
            #pragma unroll
            for (int d = 0; d < 4; d++) acc[a][b][d] = 0.f;

    uint32_t fa[2][4][4], fb[2][4][4];

    auto load_frags = [&](uint32_t sb, int ks, int buf) {
        const int kb = ks * 32;
        const uint32_t aA = sb + arow * 128 + ((kb + koffA) ^ xA);
        const uint32_t bB = sb + 16384 + brow * 128 + ((kb + koffB) ^ xB);
        #pragma unroll
        for (int mt = 0; mt < 4; mt++)
            ldsm4(fa[buf][mt][0], fa[buf][mt][1], fa[buf][mt][2], fa[buf][mt][3],
                  aA + mt * 2048);
        #pragma unroll
        for (int p = 0; p < 4; p++)
            ldsm4(fb[buf][p][0], fb[buf][p][1], fb[buf][p][2], fb[buf][p][3],
                  bB + p * 2048);
    };

    for (int c = 0; c < NCHUNK; c++) {
        asm volatile("cp.async.wait_group 2;" ::: "memory");
        __syncthreads();
        const uint32_t sb = smem_base + 1024 + (c & 3) * STAGE_BYTES;

        // first fragment batch, then kick off next chunk's loads (overlaps compute)
        load_frags(sb, 0, 0);
        const int n = c + 3;
        if (n < NCHUNK) load_chunk(n, n & 3);          // stage (c-1)&3: safe post-barrier
        else asm volatile("cp.async.commit_group;" ::: "memory");

        #pragma unroll
        for (int ks = 0; ks < 4; ks++) {
            const int cur = ks & 1;
            if (ks < 3) load_frags(sb, ks + 1, cur ^ 1);
            #pragma unroll
            for (int mt = 0; mt < 4; mt++) {
                #pragma unroll
                for (int p = 0; p < 4; p++) {
                    hmma(acc[mt][2 * p],
                         fa[cur][mt][0], fa[cur][mt][1], fa[cur][mt][2], fa[cur][mt][3],
                         fb[cur][p][0], fb[cur][p][1]);
                    hmma(acc[mt][2 * p + 1],
                         fa[cur][mt][0], fa[cur][mt][1], fa[cur][mt][2], fa[cur][mt][3],
                         fb[cur][p][2], fb[cur][p][3]);
                }
            }
        }
    }
    __syncthreads();

    // ---- epilogue: bias + per-row online LSE + target gather
    float* bias_s = (float*)(dsmem + 1024);
    if (tid < BN) bias_s[tid] = Bv[cb + tid];
    float* rmx = (float*)(dsmem + 2048);    // [128][4]
    float* rsm = rmx + 512;
    float* rtl = rsm + 512;
    __syncthreads();

    #pragma unroll
    for (int mt = 0; mt < 4; mt++) {
        #pragma unroll
        for (int half = 0; half < 2; half++) {
            const int rloc = wr * 64 + mt * 16 + (lid >> 2) + half * 8;
            const int loc  = g_target[rb + rloc] - cb;
            float m = -INFINITY;
            #pragma unroll
            for (int nt = 0; nt < 8; nt++) {
                #pragma unroll
                for (int j = 0; j < 2; j++) {
                    const int gcol = wc * 64 + nt * 8 + (lid & 3) * 2 + j;
                    m = fmaxf(m, acc[mt][nt][half * 2 + j] + bias_s[gcol]);
                }
            }
            float s = 0.f, tl = 0.f;
            #pragma unroll
            for (int nt = 0; nt < 8; nt++) {
                #pragma unroll
                for (int j = 0; j < 2; j++) {
                    const int gcol = wc * 64 + nt * 8 + (lid & 3) * 2 + j;
                    const float v = acc[mt][nt][half * 2 + j] + bias_s[gcol];
                    s += __expf(v - m);
                    if (gcol == loc) tl = v;
                }
            }
            #pragma unroll
            for (int off = 1; off <= 2; off <<= 1) {
                const float mo = __shfl_xor_sync(0xffffffffu, m, off);
                const float so = __shfl_xor_sync(0xffffffffu, s, off);
                const float nm = fmaxf(m, mo);
                s = s * __expf(m - nm) + so * __expf(mo - nm);
                m = nm;
                tl += __shfl_xor_sync(0xffffffffu, tl, off);
            }
            if ((lid & 3) == 0) {
                rmx[rloc * 4 + wc] = m;
                rsm[rloc * 4 + wc] = s;
                rtl[rloc * 4 + wc] = tl;
            }
        }
    }
    __syncthreads();

    if (tid < 128) {
        const int row = rb + tid;
        float M = rmx[tid * 4];
        #pragma unroll
        for (int wq = 1; wq < 4; wq++) M = fmaxf(M, rmx[tid * 4 + wq]);
        float S = 0.f;
        #pragma unroll
        for (int wq = 0; wq < 4; wq++)
            S += rsm[tid * 4 + wq] * __expf(rmx[tid * 4 + wq] - M);
        g_pm[model][row][nblk] = M;
        g_ps[model][row][nblk] = S;
        const int loc = g_target[row] - cb;
        if (loc >= 0 && loc < BN) {
            float tl = 0.f;
            #pragma unroll
            for (int wq = 0; wq < 4; wq++) tl += rtl[tid * 4 + wq];
            g_tgt[model][row] = tl;
        }
    }
}

// -----------------------------------------------------------------------------
// Phase B: merge per-nblock partials -> full LSE -> per-token logprob.
// -----------------------------------------------------------------------------
__global__ void lse_reduce_kernel()
{
    const int row = blockIdx.x;
    const int m   = blockIdx.y;
    const int tid = threadIdx.x;

    __shared__ float sm[4];

    float pm = -INFINITY;
    if (tid < NBLK) pm = g_pm[m][row][tid];

    float mv = pm;
    #pragma unroll
    for (int off = 16; off >= 1; off >>= 1)
        mv = fmaxf(mv, __shfl_xor_sync(0xffffffffu, mv, off));
    if ((tid & 31) == 0) sm[tid >> 5] = mv;
    __syncthreads();
    float M = fmaxf(fmaxf(sm[0], sm[1]), fmaxf(sm[2], sm[3]));
    __syncthreads();

    float sv = 0.f;
    if (tid < NBLK) sv = g_ps[m][row][tid] * expf(pm - M);
    #pragma unroll
    for (int off = 16; off >= 1; off >>= 1)
        sv += __shfl_xor_sync(0xffffffffu, sv, off);
    if ((tid & 31) == 0) sm[tid >> 5] = sv;
    __syncthreads();

    if (tid == 0) {
        const float S = sm[0] + sm[1] + sm[2] + sm[3];
        const float lse = M + logf(S);
        g_tok[m][row] = g_mask[row] ? (g_tgt[m][row] - lse) : 0.f;
    }
}

// -----------------------------------------------------------------------------
// Phase C: deterministic per-sequence sums (double) + KTO epilogue.
// -----------------------------------------------------------------------------
__global__ void final_kernel(const float* __restrict__ kl,
                             float* __restrict__ out, int out_size)
{
    __shared__ double red[TSEQ];
    __shared__ double seq[2][NSEQ];
    const int tid = threadIdx.x;

    for (int m = 0; m < 2; m++) {
        for (int b = 0; b < NSEQ; b++) {
            red[tid] = (double)g_tok[m][b * TSEQ + tid];
            __syncthreads();
            for (int s = TSEQ / 2; s > 0; s >>= 1) {
                if (tid < s) red[tid] += red[tid + s];
                __syncthreads();
            }
            if (tid == 0) seq[m][b] = red[0];
            __syncthreads();
        }
    }

    if (tid == 0) {
        const double k = (double)kl[0];
        double loss = 0.0, ch = 0.0, rj = 0.0;
        for (int b = 0; b < NSEQ; b++) {
            const double lr   = seq[0][b] - seq[1][b];
            const int    lab  = g_labels[b];
            const double mult = lab ? 1.0 : -1.0;
            const double z    = (double)BETA * (lr - k) * mult;
            const double sg   = 1.0 / (1.0 + exp(-z));
            loss += 1.0 - sg;
            const double rw = (double)BETA * lr;
            if (lab) ch += rw; else rj += rw;
        }
        loss /= (double)R_TOK;
        if (out_size > 0) out[0] = (float)loss;
        if (out_size > 1) out[1] = (float)ch;
        if (out_size > 2) out[2] = (float)rj;
    }
    for (int i = 3 + tid; i < out_size; i += blockDim.x) out[i] = 0.f;
}

// -----------------------------------------------------------------------------
// Launch
// -----------------------------------------------------------------------------
extern "C" void kernel_launch(void* const* d_in, const int* in_sizes, int n_in,
                              void* d_out, int out_size)
{
    int ix = -1, ixr = -1, iw = -1, iwr = -1, ib = -1, ibr = -1;
    int it = -1, il = -1, ikl = -1;
    for (int i = 0; i < n_in; i++) {
        const long long s = in_sizes[i];
        if      (s == (long long)R_TOK * HID) { if (ix < 0) ix = i; else ixr = i; }
        else if (s == (long long)VOC * HID)   { if (iw < 0) iw = i; else iwr = i; }
        else if (s == VOC)                    { if (ib < 0) ib = i; else ibr = i; }
        else if (s == R_TOK)                  { it = i; }
        else if (s == NSEQ)                   { il = i; }
        else if (s == 1)                      { ikl = i; }
    }
    if (ix < 0) ix = 0; if (iw < 0) iw = 1; if (it < 0) it = 2; if (ib < 0) ib = 3;
    if (il < 0) il = 4; if (ixr < 0) ixr = 5; if (iwr < 0) iwr = 6; if (ibr < 0) ibr = 7;
    if (ikl < 0) ikl = 8;

    const float* x      = (const float*)d_in[ix];
    const float* w      = (const float*)d_in[iw];
    const void*  tgt    = d_in[it];
    const float* bias   = (const float*)d_in[ib];
    const void*  labels = d_in[il];
    const float* xr     = (const float*)d_in[ixr];
    const float* wr     = (const float*)d_in[iwr];
    const float* br     = (const float*)d_in[ibr];
    const float* kl     = (const float*)d_in[ikl];

    cudaFuncSetAttribute(gemm_tc_kernel,
                         cudaFuncAttributeMaxDynamicSharedMemorySize, SMEM_TOTAL);

    detect_kernel<<<1, 256>>>(tgt, labels);

    {
        const int totX = 2 * R_TOK * (HID / 4);
        convert_x_kernel<<<(totX + 255) / 256, 256>>>(x, xr);
        const int totW = 2 * VOC * (HID / 4);
        convert_w_kernel<<<(totW + 255) / 256, 256>>>(w, wr);
    }

    gemm_tc_kernel<<<2 * MBLK * NBLK, 256, SMEM_TOTAL>>>(bias, br);

    dim3 gridB(R_TOK, 2);
    lse_reduce_kernel<<<gridB, 128>>>();

    final_kernel<<<1, TSEQ>>>(kl, (float*)d_out, out_size);
}

// round 6
// speedup vs baseline: 1.0430x; 1.0430x over previous
#include <cuda_runtime.h>
#include <cuda_bf16.h>
#include <cstdint>
#include <math.h>

// Problem constants (B=4, T=512, H=1024, V=32000)
#define R_TOK 2048
#define HID   1024
#define VOC   32000
#define NSEQ  4
#define TSEQ  512

#define KCAT  2048              // [hi | lo] storage; 3 term-pairings via offsets
#define BM    128
#define BN    256
#define NBLK  (VOC / BN)        // 125
#define MBLK  (R_TOK / BM)      // 16
#define NCHUNK 48               // 3 passes x 16 chunks of 64 K-elems
#define NSTAGE 4
#define STAGE_BYTES 49152       // A 16KB + B 32KB
#define SMEM_TOTAL (1024 + NSTAGE * STAGE_BYTES)   // 197632

#define BETA 0.1f

// ------------------------------- scratch -----------------------------------
__device__ float g_pm[2][R_TOK][NBLK];
__device__ float g_ps[2][R_TOK][NBLK];
__device__ float g_tgt[2][R_TOK];
__device__ float g_tok[2][R_TOK];
__device__ int   g_target[R_TOK];
__device__ int   g_mask[R_TOK];
__device__ int   g_labels[NSEQ];

__device__ __align__(16) __nv_bfloat16 g_A[2][R_TOK][KCAT];   // 16.8 MB
__device__ __align__(16) __nv_bfloat16 g_B[2][VOC][KCAT];     // 262 MB

// ------------------------------- helpers -----------------------------------
__device__ __forceinline__ uint32_t smem_u32(const void* p) {
    uint32_t a;
    asm("{ .reg .u64 t; cvta.to.shared.u64 t, %1; cvt.u32.u64 %0, t; }"
        : "=r"(a) : "l"(p));
    return a;
}

__device__ __forceinline__ uint32_t sw128(uint32_t o) {
    return o ^ ((o >> 3) & 0x70u);
}

__device__ __forceinline__ void cp16(uint32_t s, const void* g) {
    asm volatile("cp.async.cg.shared.global [%0], [%1], 16;" :: "r"(s), "l"(g));
}

__device__ __forceinline__ void ldsm4(uint32_t& r0, uint32_t& r1,
                                      uint32_t& r2, uint32_t& r3, uint32_t a) {
    asm volatile("ldmatrix.sync.aligned.m8n8.x4.shared.b16 {%0,%1,%2,%3}, [%4];"
                 : "=r"(r0), "=r"(r1), "=r"(r2), "=r"(r3) : "r"(a));
}

__device__ __forceinline__ void hmma(float* c, uint32_t a0, uint32_t a1,
                                     uint32_t a2, uint32_t a3,
                                     uint32_t b0, uint32_t b1) {
    asm volatile(
        "mma.sync.aligned.m16n8k16.row.col.f32.bf16.bf16.f32 "
        "{%0,%1,%2,%3}, {%4,%5,%6,%7}, {%8,%9}, {%0,%1,%2,%3};"
        : "+f"(c[0]), "+f"(c[1]), "+f"(c[2]), "+f"(c[3])
        : "r"(a0), "r"(a1), "r"(a2), "r"(a3), "r"(b0), "r"(b1));
}

// -----------------------------------------------------------------------------
// Phase 0: dtype detection + normalization of target / labels (proven)
// -----------------------------------------------------------------------------
__global__ void detect_kernel(const void* __restrict__ tgt_raw,
                              const void* __restrict__ lab_raw)
{
    __shared__ int s_t64;
    const int tid = threadIdx.x;
    const int* t32 = (const int*)tgt_raw;

    if (tid == 0) {
        bool t64 = true;
        for (int k = 0; k < 64; k++)
            if (t32[2 * k + 1] != 0) { t64 = false; break; }
        s_t64 = t64 ? 1 : 0;

        const unsigned int*  li = (const unsigned int*)lab_raw;
        const unsigned char* lb = (const unsigned char*)lab_raw;
        int done = 0;
        {
            bool isf = true;
            for (int b = 0; b < 4; b++) {
                unsigned int u = li[b];
                if (u != 0u && u != 0x3f800000u) { isf = false; break; }
            }
            if (isf) {
                for (int b = 0; b < 4; b++) g_labels[b] = (li[b] != 0u) ? 1 : 0;
                done = 1;
            }
        }
        if (!done && li[0] <= 1u) {
            bool isi = true;
            for (int b = 1; b < 4; b++)
                if (li[b] > 1u) { isi = false; break; }
            if (isi) {
                for (int b = 0; b < 4; b++) g_labels[b] = (int)li[b];
                done = 1;
            }
        }
        if (!done)
            for (int b = 0; b < 4; b++) g_labels[b] = (lb[b] != 0) ? 1 : 0;
    }
    __syncthreads();

    const bool t64 = (s_t64 != 0);
    for (int i = tid; i < R_TOK; i += blockDim.x) {
        int v = t64 ? t32[2 * i] : t32[i];
        const int ign = (v == -100);
        if (v < 0) v = 0;
        if (v > VOC - 1) v = VOC - 1;
        g_target[i] = v;
        g_mask[i]   = ign ? 0 : 1;
    }
}

// -----------------------------------------------------------------------------
// Phase 0b: fp32 -> bf16 hi/lo split: [hi | lo] (K=2048 each)
// -----------------------------------------------------------------------------
__device__ __forceinline__ void split4(const float4 v,
                                       __nv_bfloat162& h01, __nv_bfloat162& h23,
                                       __nv_bfloat162& l01, __nv_bfloat162& l23)
{
    __nv_bfloat16 h0 = __float2bfloat16_rn(v.x);
    __nv_bfloat16 h1 = __float2bfloat16_rn(v.y);
    __nv_bfloat16 h2 = __float2bfloat16_rn(v.z);
    __nv_bfloat16 h3 = __float2bfloat16_rn(v.w);
    __nv_bfloat16 l0 = __float2bfloat16_rn(v.x - __bfloat162float(h0));
    __nv_bfloat16 l1 = __float2bfloat16_rn(v.y - __bfloat162float(h1));
    __nv_bfloat16 l2 = __float2bfloat16_rn(v.z - __bfloat162float(h2));
    __nv_bfloat16 l3 = __float2bfloat16_rn(v.w - __bfloat162float(h3));
    h01 = __nv_bfloat162(h0, h1); h23 = __nv_bfloat162(h2, h3);
    l01 = __nv_bfloat162(l0, l1); l23 = __nv_bfloat162(l2, l3);
}

__global__ void convert_w_kernel(const float* __restrict__ w0,
                                 const float* __restrict__ w1)
{
    const int QPR = HID / 4;                     // 256 quads/row
    const int per_model = VOC * QPR;
    int id = blockIdx.x * blockDim.x + threadIdx.x;
    if (id >= 2 * per_model) return;
    const int m = id / per_model;
    const int r = (id % per_model) / QPR;
    const int q = id % QPR;
    const float* W = m ? w1 : w0;
    const float4 v = *(const float4*)(W + (size_t)r * HID + q * 4);
    __nv_bfloat162 h01, h23, l01, l23;
    split4(v, h01, h23, l01, l23);
    __nv_bfloat16* row = &g_B[m][r][0];
    *(__nv_bfloat162*)(row + q * 4 + 0)       = h01;   // seg0: hi
    *(__nv_bfloat162*)(row + q * 4 + 2)       = h23;
    *(__nv_bfloat162*)(row + HID + q * 4 + 0) = l01;   // seg1: lo
    *(__nv_bfloat162*)(row + HID + q * 4 + 2) = l23;
}

__global__ void convert_x_kernel(const float* __restrict__ x0,
                                 const float* __restrict__ x1)
{
    const int QPR = HID / 4;
    const int per_model = R_TOK * QPR;
    int id = blockIdx.x * blockDim.x + threadIdx.x;
    if (id >= 2 * per_model) return;
    const int m = id / per_model;
    const int r = (id % per_model) / QPR;
    const int q = id % QPR;
    const float* X = m ? x1 : x0;
    const float4 v = *(const float4*)(X + (size_t)r * HID + q * 4);
    __nv_bfloat162 h01, h23, l01, l23;
    split4(v, h01, h23, l01, l23);
    __nv_bfloat16* row = &g_A[m][r][0];
    *(__nv_bfloat162*)(row + q * 4 + 0)       = h01;   // seg0: hi
    *(__nv_bfloat162*)(row + q * 4 + 2)       = h23;
    *(__nv_bfloat162*)(row + HID + q * 4 + 0) = l01;   // seg1: lo
    *(__nv_bfloat162*)(row + HID + q * 4 + 2) = l23;
}

// -----------------------------------------------------------------------------
// Phase A: HMMA bf16 GEMM, CTA tile 128x256, warp tile 64x64 (2x4 warps).
// 48 chunks of K=64: c<16:(Ahi,Bhi) 16..31:(Ahi,Blo) 32..47:(Alo,Bhi).
// R4-proven loop structure: inline per-ks ldsm (no double buffer), loads after
// compute. 4-stage cp.async pipeline.
// -----------------------------------------------------------------------------
extern __shared__ char dsmem[];

__global__ void __launch_bounds__(256, 1)
gemm_tc_kernel(const float* __restrict__ b_pol, const float* __restrict__ b_ref)
{
    const int bx    = blockIdx.x;
    const int mblk  = bx & (MBLK - 1);
    const int t     = bx >> 4;
    const int nblk  = t % NBLK;
    const int model = t / NBLK;
    const int rb    = mblk * BM;
    const int cb    = nblk * BN;
    const float* __restrict__ Bv = model ? b_ref : b_pol;

    const int tid = threadIdx.x;
    const int wid = tid >> 5;
    const int lid = tid & 31;

    const uint32_t smem_base = smem_u32(dsmem);

    const char* Agm = (const char*)&g_A[model][rb][0];
    const char* Bgm = (const char*)&g_B[model][cb][0];
    const size_t rowbytes = (size_t)KCAT * 2;   // 4096

    // chunk -> segment offsets (in 128-byte k-units)
    auto a_koff = [](int c) -> int { return (c >= 32) ? 16 + (c & 15) : (c & 15); };
    auto b_koff = [](int c) -> int { return ((c >> 4) == 1) ? 16 + (c & 15) : (c & 15); };

    // ---- tile loader: chunk c -> stage s
    auto load_chunk = [&](int c, int s) {
        const uint32_t abase = smem_base + 1024 + s * STAGE_BYTES;
        const uint32_t bbase = abase + 16384;
        const char* ag = Agm + (size_t)a_koff(c) * 128;
        const char* bg = Bgm + (size_t)b_koff(c) * 128;
        #pragma unroll
        for (int i = 0; i < 4; i++) {               // A: 1024 x 16B
            const int q = tid + 256 * i;
            const int row = q >> 3, x = q & 7;
            cp16(abase + sw128(row * 128 + x * 16), ag + (size_t)row * rowbytes + x * 16);
        }
        #pragma unroll
        for (int i = 0; i < 8; i++) {               // B: 2048 x 16B
            const int q = tid + 256 * i;
            const int row = q >> 3, x = q & 7;
            cp16(bbase + sw128(row * 128 + x * 16), bg + (size_t)row * rowbytes + x * 16);
        }
        asm volatile("cp.async.commit_group;" ::: "memory");
    };

    load_chunk(0, 0);
    load_chunk(1, 1);
    load_chunk(2, 2);

    // warp mapping: 64x64 tiles, 2 (M) x 4 (N)
    const int wr = wid & 1;
    const int wc = wid >> 1;

    // ldsm addressing (per-lane swizzle reduces to constant XOR)
    const int koffA = (lid >> 4) * 16;
    const int xA    = (lid & 7) << 4;
    const int arow  = wr * 64 + (lid & 15);
    const int rbB   = (lid >> 4) * 8 + (lid & 7);      // 0..15
    const int koffB = ((lid >> 3) & 1) * 16;
    const int xB    = (rbB & 7) << 4;
    const int brow  = wc * 64 + rbB;

    float acc[4][8][4];
    #pragma unroll
    for (int a = 0; a < 4; a++)
        #pragma unroll
        for (int b = 0; b < 8; b++)
            #pragma unroll
            for (int d = 0; d < 4; d++) acc[a][b][d] = 0.f;

    for (int c = 0; c < NCHUNK; c++) {
        asm volatile("cp.async.wait_group 2;" ::: "memory");
        __syncthreads();
        const uint32_t sb  = smem_base + 1024 + (c & 3) * STAGE_BYTES;
        const uint32_t aA  = sb + arow * 128;
        const uint32_t bB  = sb + 16384 + brow * 128;

        #pragma unroll
        for (int ks = 0; ks < 4; ks++) {
            const int kb = ks * 32;
            uint32_t a[4][4];
            #pragma unroll
            for (int mt = 0; mt < 4; mt++)
                ldsm4(a[mt][0], a[mt][1], a[mt][2], a[mt][3],
                      aA + mt * 2048 + ((kb + koffA) ^ xA));
            #pragma unroll
            for (int p = 0; p < 4; p++) {
                uint32_t b0, b1, b2, b3;
                ldsm4(b0, b1, b2, b3, bB + p * 2048 + ((kb + koffB) ^ xB));
                #pragma unroll
                for (int mt = 0; mt < 4; mt++) {
                    hmma(acc[mt][2 * p],
                         a[mt][0], a[mt][1], a[mt][2], a[mt][3], b0, b1);
                    hmma(acc[mt][2 * p + 1],
                         a[mt][0], a[mt][1], a[mt][2], a[mt][3], b2, b3);
                }
            }
        }
        const int n = c + 3;
        if (n < NCHUNK) load_chunk(n, n & 3);
        else asm volatile("cp.async.commit_group;" ::: "memory");
    }
    asm volatile("cp.async.wait_group 0;" ::: "memory");
    __syncthreads();

    // ---- epilogue: bias + per-row online LSE + target gather (proven in R5)
    float* bias_s = (float*)(dsmem + 1024);
    if (tid < BN) bias_s[tid] = Bv[cb + tid];
    float* rmx = (float*)(dsmem + 2048);    // [128][4]
    float* rsm = rmx + 512;
    float* rtl = rsm + 512;
    __syncthreads();

    #pragma unroll
    for (int mt = 0; mt < 4; mt++) {
        #pragma unroll
        for (int half = 0; half < 2; half++) {
            const int rloc = wr * 64 + mt * 16 + (lid >> 2) + half * 8;
            const int loc  = g_target[rb + rloc] - cb;
            float m = -INFINITY;
            #pragma unroll
            for (int nt = 0; nt < 8; nt++) {
                #pragma unroll
                for (int j = 0; j < 2; j++) {
                    const int gcol = wc * 64 + nt * 8 + (lid & 3) * 2 + j;
                    m = fmaxf(m, acc[mt][nt][half * 2 + j] + bias_s[gcol]);
                }
            }
            float s = 0.f, tl = 0.f;
            #pragma unroll
            for (int nt = 0; nt < 8; nt++) {
                #pragma unroll
                for (int j = 0; j < 2; j++) {
                    const int gcol = wc * 64 + nt * 8 + (lid & 3) * 2 + j;
                    const float v = acc[mt][nt][half * 2 + j] + bias_s[gcol];
                    s += __expf(v - m);
                    if (gcol == loc) tl = v;
                }
            }
            #pragma unroll
            for (int off = 1; off <= 2; off <<= 1) {
                const float mo = __shfl_xor_sync(0xffffffffu, m, off);
                const float so = __shfl_xor_sync(0xffffffffu, s, off);
                const float nm = fmaxf(m, mo);
                s = s * __expf(m - nm) + so * __expf(mo - nm);
                m = nm;
                tl += __shfl_xor_sync(0xffffffffu, tl, off);
            }
            if ((lid & 3) == 0) {
                rmx[rloc * 4 + wc] = m;
                rsm[rloc * 4 + wc] = s;
                rtl[rloc * 4 + wc] = tl;
            }
        }
    }
    __syncthreads();

    if (tid < 128) {
        const int row = rb + tid;
        float M = rmx[tid * 4];
        #pragma unroll
        for (int wq = 1; wq < 4; wq++) M = fmaxf(M, rmx[tid * 4 + wq]);
        float S = 0.f;
        #pragma unroll
        for (int wq = 0; wq < 4; wq++)
            S += rsm[tid * 4 + wq] * __expf(rmx[tid * 4 + wq] - M);
        g_pm[model][row][nblk] = M;
        g_ps[model][row][nblk] = S;
        const int loc = g_target[row] - cb;
        if (loc >= 0 && loc < BN) {
            float tl = 0.f;
            #pragma unroll
            for (int wq = 0; wq < 4; wq++) tl += rtl[tid * 4 + wq];
            g_tgt[model][row] = tl;
        }
    }
}

// -----------------------------------------------------------------------------
// Phase B: merge per-nblock partials -> full LSE -> per-token logprob.
// -----------------------------------------------------------------------------
__global__ void lse_reduce_kernel()
{
    const int row = blockIdx.x;
    const int m   = blockIdx.y;
    const int tid = threadIdx.x;

    __shared__ float sm[4];

    float pm = -INFINITY;
    if (tid < NBLK) pm = g_pm[m][row][tid];

    float mv = pm;
    #pragma unroll
    for (int off = 16; off >= 1; off >>= 1)
        mv = fmaxf(mv, __shfl_xor_sync(0xffffffffu, mv, off));
    if ((tid & 31) == 0) sm[tid >> 5] = mv;
    __syncthreads();
    float M = fmaxf(fmaxf(sm[0], sm[1]), fmaxf(sm[2], sm[3]));
    __syncthreads();

    float sv = 0.f;
    if (tid < NBLK) sv = g_ps[m][row][tid] * expf(pm - M);
    #pragma unroll
    for (int off = 16; off >= 1; off >>= 1)
        sv += __shfl_xor_sync(0xffffffffu, sv, off);
    if ((tid & 31) == 0) sm[tid >> 5] = sv;
    __syncthreads();

    if (tid == 0) {
        const float S = sm[0] + sm[1] + sm[2] + sm[3];
        const float lse = M + logf(S);
        g_tok[m][row] = g_mask[row] ? (g_tgt[m][row] - lse) : 0.f;
    }
}

// -----------------------------------------------------------------------------
// Phase C: deterministic per-sequence sums (double) + KTO epilogue.
// -----------------------------------------------------------------------------
__global__ void final_kernel(const float* __restrict__ kl,
                             float* __restrict__ out, int out_size)
{
    __shared__ double red[TSEQ];
    __shared__ double seq[2][NSEQ];
    const int tid = threadIdx.x;

    for (int m = 0; m < 2; m++) {
        for (int b = 0; b < NSEQ; b++) {
            red[tid] = (double)g_tok[m][b * TSEQ + tid];
            __syncthreads();
            for (int s = TSEQ / 2; s > 0; s >>= 1) {
                if (tid < s) red[tid] += red[tid + s];
                __syncthreads();
            }
            if (tid == 0) seq[m][b] = red[0];
            __syncthreads();
        }
    }

    if (tid == 0) {
        const double k = (double)kl[0];
        double loss = 0.0, ch = 0.0, rj = 0.0;
        for (int b = 0; b < NSEQ; b++) {
            const double lr   = seq[0][b] - seq[1][b];
            const int    lab  = g_labels[b];
            const double mult = lab ? 1.0 : -1.0;
            const double z    = (double)BETA * (lr - k) * mult;
            const double sg   = 1.0 / (1.0 + exp(-z));
            loss += 1.0 - sg;
            const double rw = (double)BETA * lr;
            if (lab) ch += rw; else rj += rw;
        }
        loss /= (double)R_TOK;
        if (out_size > 0) out[0] = (float)loss;
        if (out_size > 1) out[1] = (float)ch;
        if (out_size > 2) out[2] = (float)rj;
    }
    for (int i = 3 + tid; i < out_size; i += blockDim.x) out[i] = 0.f;
}

// -----------------------------------------------------------------------------
// Launch
// -----------------------------------------------------------------------------
extern "C" void kernel_launch(void* const* d_in, const int* in_sizes, int n_in,
                              void* d_out, int out_size)
{
    int ix = -1, ixr = -1, iw = -1, iwr = -1, ib = -1, ibr = -1;
    int it = -1, il = -1, ikl = -1;
    for (int i = 0; i < n_in; i++) {
        const long long s = in_sizes[i];
        if      (s == (long long)R_TOK * HID) { if (ix < 0) ix = i; else ixr = i; }
        else if (s == (long long)VOC * HID)   { if (iw < 0) iw = i; else iwr = i; }
        else if (s == VOC)                    { if (ib < 0) ib = i; else ibr = i; }
        else if (s == R_TOK)                  { it = i; }
        else if (s == NSEQ)                   { il = i; }
        else if (s == 1)                      { ikl = i; }
    }
    if (ix < 0) ix = 0; if (iw < 0) iw = 1; if (it < 0) it = 2; if (ib < 0) ib = 3;
    if (il < 0) il = 4; if (ixr < 0) ixr = 5; if (iwr < 0) iwr = 6; if (ibr < 0) ibr = 7;
    if (ikl < 0) ikl = 8;

    const float* x      = (const float*)d_in[ix];
    const float* w      = (const float*)d_in[iw];
    const void*  tgt    = d_in[it];
    const float* bias   = (const float*)d_in[ib];
    const void*  labels = d_in[il];
    const float* xr     = (const float*)d_in[ixr];
    const float* wr     = (const float*)d_in[iwr];
    const float* br     = (const float*)d_in[ibr];
    const float* kl     = (const float*)d_in[ikl];

    cudaFuncSetAttribute(gemm_tc_kernel,
                         cudaFuncAttributeMaxDynamicSharedMemorySize, SMEM_TOTAL);

    detect_kernel<<<1, 256>>>(tgt, labels);

    {
        const int totX = 2 * R_TOK * (HID / 4);
        convert_x_kernel<<<(totX + 255) / 256, 256>>>(x, xr);
        const int totW = 2 * VOC * (HID / 4);
        convert_w_kernel<<<(totW + 255) / 256, 256>>>(w, wr);
    }

    gemm_tc_kernel<<<2 * MBLK * NBLK, 256, SMEM_TOTAL>>>(bias, br);

    dim3 gridB(R_TOK, 2);
    lse_reduce_kernel<<<gridB, 128>>>();

    final_kernel<<<1, TSEQ>>>(kl, (float*)d_out, out_size);
}